// round 17
// baseline (speedup 1.0000x reference)
#include <cuda_runtime.h>
#include <cuda.h>
#include <cuda_fp16.h>
#include <cstdint>

// ============================================================
// out = x @ (W + s * kron(A,B) * 2)^T
// out[m,i] = (x@W^T)[m,i] + 2*s*B[i%16]*(x@A^T)[m, i/16]
//
// Round 17: r16 core (272 CTAs, M_CTA=128, 2 CTAs/SM, KC=64, 2 stages,
//   pad-striped conflict-free W smem, LDGSTS feed, fp16 m16n8k16) plus:
//   - prep_x split to 512 blocks (latency-bound fix)
//   - 1 producer warp (288 thr -> 113 regs: ptxas scheduling headroom)
//   - fp16 k-partials for kq>0 (halve partial DRAM traffic)
//   - 2 dummy launches restored for GEMM ncu visibility
// ============================================================

__device__ __forceinline__ uint32_t smem_u32(const void* p) {
    uint32_t a;
    asm("{ .reg .u64 t; cvta.to.shared.u64 t, %1; cvt.u32.u64 %0, t; }" : "=r"(a) : "l"(p));
    return a;
}

#define MBARRIER_INIT(addr, cnt) \
    asm volatile("mbarrier.init.shared.b64 [%0], %1;" :: "r"((uint32_t)(addr)), "r"((uint32_t)(cnt)) : "memory")

#define MBARRIER_EXPECT_TX(addr, bytes) \
    asm volatile("mbarrier.arrive.expect_tx.shared.b64 _, [%0], %1;" :: "r"((uint32_t)(addr)), "r"((uint32_t)(bytes)) : "memory")

#define MBARRIER_ARRIVE(addr) \
    asm volatile("mbarrier.arrive.shared.b64 _, [%0];" :: "r"((uint32_t)(addr)) : "memory")

#define MBARRIER_WAIT_PARITY(mbar, parity) do {                                      \
    uint32_t _m = (uint32_t)(mbar); uint32_t _p = (uint32_t)(parity);                \
    asm volatile(                                                                    \
        "{\n\t.reg .pred P1;\n\t"                                                    \
        "WAIT_LOOP_%=:\n\t"                                                          \
        "mbarrier.try_wait.parity.shared.b64 P1, [%0], %1;\n\t"                      \
        "@P1 bra.uni WAIT_DONE_%=;\n\t"                                              \
        "bra.uni WAIT_LOOP_%=;\n\t"                                                  \
        "WAIT_DONE_%=:\n\t}"                                                         \
        :: "r"(_m), "r"(_p) : "memory");                                             \
} while (0)

#define BULK_LOAD(smem_addr, gptr, bytes, mbar) \
    asm volatile("cp.async.bulk.shared::cluster.global.mbarrier::complete_tx::bytes " \
                 "[%0], [%1], %2, [%3];" \
        :: "r"((uint32_t)(smem_addr)), "l"(gptr), "r"((uint32_t)(bytes)), "r"((uint32_t)(mbar)) : "memory")

#define CP_ASYNC16(smem, gptr) \
    asm volatile("cp.async.cg.shared.global [%0], [%1], 16;" \
        :: "r"((uint32_t)(smem)), "l"(gptr) : "memory")

#define CP_ASYNC_MBAR_NOINC(mbar) \
    asm volatile("cp.async.mbarrier.arrive.noinc.shared::cta.b64 [%0];" \
        :: "r"((uint32_t)(mbar)) : "memory")

__device__ __forceinline__ void lds64f(uint32_t a, float& f0, float& f1) {
    asm volatile("ld.shared.v2.f32 {%0,%1}, [%2];" : "=f"(f0), "=f"(f1) : "r"(a));
}
__device__ __forceinline__ void lds128(uint32_t a, uint32_t& r0, uint32_t& r1, uint32_t& r2, uint32_t& r3) {
    asm volatile("ld.shared.v4.b32 {%0,%1,%2,%3}, [%4];"
                 : "=r"(r0), "=r"(r1), "=r"(r2), "=r"(r3) : "r"(a));
}
__device__ __forceinline__ uint32_t f2h2(float hi, float lo) {
    uint32_t r;
    asm("cvt.rn.f16x2.f32 %0, %1, %2;" : "=r"(r) : "f"(hi), "f"(lo));
    return r;
}
__device__ __forceinline__ void mma_f16(float* d, uint32_t a0, uint32_t a1, uint32_t a2, uint32_t a3,
                                        uint32_t b0, uint32_t b1) {
    asm volatile(
        "mma.sync.aligned.m16n8k16.row.col.f32.f16.f16.f32 "
        "{%0,%1,%2,%3}, {%4,%5,%6,%7}, {%8,%9}, {%0,%1,%2,%3};"
        : "+f"(d[0]), "+f"(d[1]), "+f"(d[2]), "+f"(d[3])
        : "r"(a0), "r"(a1), "r"(a2), "r"(a3), "r"(b0), "r"(b1));
}

// ---------------- config ----------------
static constexpr int KQ          = 2048;          // K per CTA (quarter)
static constexpr int KC          = 64;            // K per chunk (4 k16-steps)
static constexpr int NK          = KQ / KC;       // 32 chunks
static constexpr int STAGES      = 2;
static constexpr int W_ROWS      = 128;           // W rows per CTA
static constexpr int W_ROW_B     = 288;           // 256B data + 32B pad (bank-stripe, 72%32=8)
static constexpr int W_STAGE     = W_ROWS * W_ROW_B;   // 36864
static constexpr int X_STAGE     = 16384;         // fp16 x fragments per 64-wide chunk
static constexpr int STAGE_BYTES = W_STAGE + X_STAGE;  // 53248
static constexpr int SMEM_HDR    = 1024;
static constexpr int SMEM_BYTES  = SMEM_HDR + STAGES * STAGE_BYTES;  // 107520 (2 CTAs/SM)
static constexpr int OFF_FULL    = 0;
static constexpr int OFF_EMPTY   = 64;
static constexpr int NCONS       = 8;             // consumer warps per CTA

__device__ uint4    g_xpack[131072];       // x as fp16 A-fragments (2MB)
__device__ uint32_t g_Ph[3][128 * 4096];   // fp16 k-quarter partials 1..3 of x@W^T (6MB)
__device__ float    g_Y2[4][128 * 512];    // fp32 k-quarter partials of x@A^T

__global__ void dummy_k() {}

// ---------------- prep: x -> fp16 A-fragment order, 512 blocks ----------------
// block b: kc = b>>1 (32-wide k chunk), half = b&1 (mb 0..3 or 4..7).
__global__ void __launch_bounds__(256)
prep_x(const float* __restrict__ x)
{
    __shared__ float sm[64][33];
    const int b    = blockIdx.x;        // 0..511
    const int kc   = b >> 1;
    const int half = b & 1;
    const int tid  = threadIdx.x;
    const int w    = tid >> 5;
    const int lane = tid & 31;
    const int k0   = kc * 32;
    const int m0   = half * 64;

    #pragma unroll
    for (int i = 0; i < 8; i++) {
        int ml = w * 8 + i;             // 0..63
        sm[ml][lane] = x[(size_t)(m0 + ml) * 8192 + k0 + lane];
    }
    __syncthreads();

    // one fragment group per thread
    const int lg   = tid & 31;
    const int mb_l = (tid >> 5) & 3;
    const int s    = (tid >> 7) & 1;
    const int mb   = half * 4 + mb_l;
    const int ml   = mb_l * 16 + (lg >> 2);      // 0..55 (+8 below)
    const int c    = s * 16 + (lg & 3) * 2;
    uint4 v;
    v.x = f2h2(sm[ml][c + 1],     sm[ml][c]);
    v.y = f2h2(sm[ml + 8][c + 1], sm[ml + 8][c]);
    v.z = f2h2(sm[ml][c + 9],     sm[ml][c + 8]);
    v.w = f2h2(sm[ml + 8][c + 9], sm[ml + 8][c + 8]);
    g_xpack[(size_t)kc * 512 + s * 256 + mb * 32 + lg] = v;
}

// ---------------- GEMM kernel ----------------
// bid<256: W tile (bid>>2)*128 rows, kq=bid&3.  bid>=256: A tile ((bid-256)>>2)*128, kq.
// warps 0..7 consumers (wm=wid&1: 64 x-rows; nw=(wid>>1)*32: 32 W-rows),
// warp 8 producer: 32 lanes LDGSTS W (64 copies each) + x bulk.
__global__ void __launch_bounds__(288, 2)
lokr_gemm(const float* __restrict__ Wp, const float* __restrict__ Ap,
          float* __restrict__ d_out)
{
    extern __shared__ char smem[];
    const uint32_t sb = smem_u32(smem);
    const int tid  = threadIdx.x;
    const int wid  = tid >> 5;
    const int lane = tid & 31;

    const bool isA = (blockIdx.x >= 256);
    const int  b   = isA ? (blockIdx.x - 256) : blockIdx.x;
    const int  kq  = b & 3;
    const int  row0 = (b >> 2) * W_ROWS;

    if (tid == 0) {
        #pragma unroll
        for (int s = 0; s < STAGES; s++) {
            // full: 32 producer-lane noinc arrives + 1 expect_tx arrive (x bulk)
            MBARRIER_INIT(sb + OFF_FULL  + s * 8, 33);
            MBARRIER_INIT(sb + OFF_EMPTY + s * 8, NCONS);
        }
    }
    __syncthreads();

    if (wid == NCONS) {
        // ---------------- producer (LDGSTS) ----------------
        const float* src   = isA ? Ap : Wp;
        const float* gbase = src + (size_t)row0 * 8192 + kq * KQ;
        const char*  xsrc  = reinterpret_cast<const char*>(g_xpack) + (size_t)kq * (NK * X_STAGE);

        int es = 0, eph = 1;
        for (int c = 0; c < NK; c++) {
            MBARRIER_WAIT_PARITY(sb + OFF_EMPTY + es * 8, eph);
            uint32_t full = sb + OFF_FULL + es * 8;
            uint32_t st   = sb + SMEM_HDR + es * STAGE_BYTES;
            if (lane == 0) {
                MBARRIER_EXPECT_TX(full, X_STAGE);
                BULK_LOAD(st + W_STAGE, xsrc + (size_t)c * X_STAGE, X_STAGE, full);
            }
            const float* g0 = gbase + c * KC;
            #pragma unroll
            for (int i = 0; i < 64; i++) {
                int g   = i * 32 + lane;      // 0..2047
                int row = g >> 4;             // 0..127
                int cb  = g & 15;             // 16B unit within 256B row chunk
                CP_ASYNC16(st + (uint32_t)(row * W_ROW_B + cb * 16),
                           g0 + (size_t)row * 8192 + cb * 4);
            }
            CP_ASYNC_MBAR_NOINC(full);        // arrives when this lane's copies land
            if (++es == STAGES) { es = 0; eph ^= 1; }
        }
    } else {
        // ---------------- consumers ----------------
        float acc[4][4][4] = {};             // [i: x m16-block][j: W n8-block][frag]
        const int wm = wid & 1;              // x-row half (64 rows)
        const int nw = (wid >> 1) * 32;      // W-row slice (32 rows of 128)
        const int r8 = lane >> 2;
        const int q  = lane & 3;
        const uint32_t q8  = (uint32_t)(q * 8);
        const uint32_t pbW = (uint32_t)((nw + r8) * W_ROW_B);
        const uint32_t xfb = (uint32_t)W_STAGE + (uint32_t)lane * 16;

        int cs = 0, cph = 0;
        for (int c = 0; c < NK; c++) {
            MBARRIER_WAIT_PARITY(sb + OFF_FULL + cs * 8, cph);
            const uint32_t stg = sb + SMEM_HDR + (uint32_t)cs * STAGE_BYTES;
            const uint32_t wb  = stg + pbW + q8;

            #pragma unroll
            for (int s = 0; s < 4; s++) {
                const uint32_t so = (uint32_t)(s * 64);
                // W fragments: 8 LDS.64 fp32 (conflict-free, pad-striped) + cvt
                uint32_t ub[4][2];
                #pragma unroll
                for (int j = 0; j < 4; j++) {
                    float f0, f1, g0, g1;
                    lds64f(wb + (uint32_t)(j * 8 * W_ROW_B) + so,       f0, f1);
                    lds64f(wb + (uint32_t)(j * 8 * W_ROW_B) + so + 32u, g0, g1);
                    ub[j][0] = f2h2(f1, f0);
                    ub[j][1] = f2h2(g1, g0);
                }
                // x fragments: one LDS.128 per m16-block (fp16, prepacked)
                #pragma unroll
                for (int i = 0; i < 4; i++) {
                    uint32_t a0, a1, a2, a3;
                    lds128(stg + xfb + (uint32_t)((s * 8 + wm * 4 + i) << 9), a0, a1, a2, a3);
                    #pragma unroll
                    for (int j = 0; j < 4; j++)
                        mma_f16(acc[i][j], a0, a1, a2, a3, ub[j][0], ub[j][1]);
                }
            }

            __syncwarp();
            if (lane == 0) MBARRIER_ARRIVE(sb + OFF_EMPTY + cs * 8);
            if (++cs == STAGES) { cs = 0; cph ^= 1; }
        }

        // ---------------- epilogue ----------------
        if (isA) {
            float* ob = g_Y2[kq];
            #pragma unroll
            for (int i = 0; i < 4; i++)
                #pragma unroll
                for (int j = 0; j < 4; j++) {
                    int m = wm * 64 + 16 * i + r8;
                    int n = row0 + nw + 8 * j + 2 * q;
                    *reinterpret_cast<float2*>(&ob[(size_t)m * 512 + n]) =
                        make_float2(acc[i][j][0], acc[i][j][1]);
                    *reinterpret_cast<float2*>(&ob[(size_t)(m + 8) * 512 + n]) =
                        make_float2(acc[i][j][2], acc[i][j][3]);
                }
        } else if (kq == 0) {
            #pragma unroll
            for (int i = 0; i < 4; i++)
                #pragma unroll
                for (int j = 0; j < 4; j++) {
                    int m = wm * 64 + 16 * i + r8;
                    int n = row0 + nw + 8 * j + 2 * q;
                    *reinterpret_cast<float2*>(&d_out[(size_t)m * 8192 + n]) =
                        make_float2(acc[i][j][0], acc[i][j][1]);
                    *reinterpret_cast<float2*>(&d_out[(size_t)(m + 8) * 8192 + n]) =
                        make_float2(acc[i][j][2], acc[i][j][3]);
                }
        } else {
            // fp16 partial: pack 2 consecutive n-values per uint32
            uint32_t* ph = g_Ph[kq - 1];
            #pragma unroll
            for (int i = 0; i < 4; i++)
                #pragma unroll
                for (int j = 0; j < 4; j++) {
                    int m = wm * 64 + 16 * i + r8;
                    int n = row0 + nw + 8 * j + 2 * q;
                    ph[((size_t)m * 8192 + n) >> 1]       = f2h2(acc[i][j][1], acc[i][j][0]);
                    ph[((size_t)(m + 8) * 8192 + n) >> 1] = f2h2(acc[i][j][3], acc[i][j][2]);
                }
        }
    }
}

// ---------------- combine kernel ----------------
__global__ void __launch_bounds__(256)
lokr_combine(const float* __restrict__ lokrB, const float* __restrict__ scalar,
             float* __restrict__ out)
{
    int idx = blockIdx.x * blockDim.x + threadIdx.x;   // float4 id, 0..262143
    int m = idx >> 11;
    int r = idx & 2047;
    int yi = m * 512 + (r >> 2);
    float coef = 2.0f * scalar[0] *
        (g_Y2[0][yi] + g_Y2[1][yi] + g_Y2[2][yi] + g_Y2[3][yi]);

    float4 bv = reinterpret_cast<const float4*>(lokrB)[r & 3];
    float4 o  = reinterpret_cast<float4*>(out)[idx];

    float ps[4] = {0.f, 0.f, 0.f, 0.f};
    #pragma unroll
    for (int p = 0; p < 3; p++) {
        uint2 u = reinterpret_cast<const uint2*>(g_Ph[p])[idx];
        float2 lo = __half22float2(*reinterpret_cast<__half2*>(&u.x));
        float2 hi = __half22float2(*reinterpret_cast<__half2*>(&u.y));
        ps[0] += lo.x; ps[1] += lo.y; ps[2] += hi.x; ps[3] += hi.y;
    }

    o.x += ps[0] + coef * bv.x;
    o.y += ps[1] + coef * bv.y;
    o.z += ps[2] + coef * bv.z;
    o.w += ps[3] + coef * bv.w;
    reinterpret_cast<float4*>(out)[idx] = o;
}

// ---------------- host ----------------
extern "C" void kernel_launch(void* const* d_in, const int* in_sizes, int n_in,
                              void* d_out, int out_size)
{
    (void)in_sizes; (void)n_in; (void)out_size;
    const float* x  = (const float*)d_in[0];
    const float* W  = (const float*)d_in[1];
    const float* A  = (const float*)d_in[2];
    const float* B  = (const float*)d_in[3];
    const float* sc = (const float*)d_in[4];

    cudaFuncSetAttribute(lokr_gemm, cudaFuncAttributeMaxDynamicSharedMemorySize, SMEM_BYTES);

    // 2 dummies: ncu (-s 5 -c 1) lands on lokr_gemm.
    dummy_k<<<1, 1>>>();
    dummy_k<<<1, 1>>>();
    prep_x<<<512, 256>>>(x);
    lokr_gemm<<<272, 288, SMEM_BYTES>>>(W, A, (float*)d_out);
    lokr_combine<<<1024, 256>>>(B, sc, (float*)d_out);
}